// round 15
// baseline (speedup 1.0000x reference)
#include <cuda_runtime.h>
#include <cuda_fp16.h>
#include <math.h>
#include <stdint.h>

#define NROWS 8192
#define DIM   512
#define NG    64
#define CAP   256

// ---------------------------------------------------------------------------
// Scratch (static device globals — zero-initialized, no runtime allocation).
// ---------------------------------------------------------------------------
__device__ __half g_xh [NROWS * DIM];          // x fp16
__device__ __half g_qh [NROWS * DIM];          // Q fp16
__device__ __half g_khi[NROWS * DIM];          // K hi/lo fp16
__device__ __half g_klo[NROWS * DIM];
__device__ float  g_V  [NROWS * DIM];          // V fp32 (for VT build)
__device__ __half g_ah [NROWS * DIM];          // attention output fp16
__device__ __half g_whi[4][DIM * DIM];         // W^T hi/lo fp16 [N][K]
__device__ __half g_wlo[4][DIM * DIM];

__device__ int    g_list[NG][CAP];
__device__ int    g_cnt[NG];
__device__ float  g_S  [NG][CAP * CAP];        // scaled scores fp32
__device__ __half g_Ph [NG][CAP * CAP];        // softmax probs fp16
__device__ __half g_VThi[NG][DIM * CAP];       // V^T hi/lo fp16 [dim][key]
__device__ __half g_VTlo[NG][DIM * CAP];

// ---------------------------------------------------------------------------
// Helpers (baseline sm_103 ISA)
// ---------------------------------------------------------------------------
__device__ __forceinline__ uint32_t smem_to_u32(const void* p) {
    uint32_t a;
    asm("{ .reg .u64 t; cvta.to.shared.u64 t, %1; cvt.u32.u64 %0, t; }" : "=r"(a) : "l"(p));
    return a;
}
__device__ __forceinline__ void cp_async16(uint32_t s, const void* g) {
    asm volatile("cp.async.cg.shared.global [%0], [%1], 16;" :: "r"(s), "l"(g));
}
__device__ __forceinline__ void cp_commit() { asm volatile("cp.async.commit_group;" ::: "memory"); }
__device__ __forceinline__ void cp_wait1()  { asm volatile("cp.async.wait_group 1;" ::: "memory"); }
__device__ __forceinline__ void cp_wait0()  { asm volatile("cp.async.wait_group 0;" ::: "memory"); }

__device__ __forceinline__ void ldsm_x4(uint32_t* r, uint32_t addr) {
    asm volatile("ldmatrix.sync.aligned.m8n8.x4.shared.b16 {%0,%1,%2,%3}, [%4];"
                 : "=r"(r[0]), "=r"(r[1]), "=r"(r[2]), "=r"(r[3]) : "r"(addr));
}
__device__ __forceinline__ void mma16816(float* d, const uint32_t* a, uint32_t b0, uint32_t b1) {
    asm volatile(
        "mma.sync.aligned.m16n8k16.row.col.f32.f16.f16.f32 "
        "{%0,%1,%2,%3}, {%4,%5,%6,%7}, {%8,%9}, {%0,%1,%2,%3};"
        : "+f"(d[0]), "+f"(d[1]), "+f"(d[2]), "+f"(d[3])
        : "r"(a[0]), "r"(a[1]), "r"(a[2]), "r"(a[3]), "r"(b0), "r"(b1));
}

// ---------------------------------------------------------------------------
// Shared HMMA core: A single fp16, B = hi + lo fp16 (2-term).
// Stage = 3 tiles (A, Bh, Bl) of 128 rows x 64 halves, row stride 144 B.
// 2 CTAs/SM (launch_bounds): 221 KB smem + full RF -> latency hiding.
// ---------------------------------------------------------------------------
static constexpr int TILE_BYTES = 128 * 144;           // 18432
static constexpr int STAGE3     = 3 * TILE_BYTES;      // 55296
static constexpr int SMEM3      = 2 * STAGE3;          // 110592

__device__ __forceinline__ void load_tile2(
    uint32_t sdst, const char* src, size_t stride_b, int rowbase, int kc, int tid)
{
#pragma unroll
    for (int i = 0; i < 4; i++) {
        int f   = tid + i * 256;
        int row = f >> 3;
        int c   = f & 7;
        cp_async16(sdst + row * 144 + c * 16,
                   src + (size_t)(rowbase + row) * stride_b + (size_t)kc * 128 + c * 16);
    }
}
__device__ __forceinline__ void load_tile_idx(
    uint32_t sdst, const char* src, const int* rows, int kc, int tid)
{
#pragma unroll
    for (int i = 0; i < 4; i++) {
        int f   = tid + i * 256;
        int row = f >> 3;
        int c   = f & 7;
        cp_async16(sdst + row * 144 + c * 16,
                   src + (size_t)rows[row] * 1024 + (size_t)kc * 128 + c * 16);
    }
}

__device__ __forceinline__ void mma_chunk2(
    uint32_t cur, int rowA, int rowB, int khalf, float acc[4][4][4])
{
    const uint32_t sA  = cur;
    const uint32_t sBh = cur + TILE_BYTES;
    const uint32_t sBl = cur + 2 * TILE_BYTES;
#pragma unroll
    for (int ks = 0; ks < 4; ks++) {
        const int ke = ks * 16 + khalf;
        uint32_t a[4][4], bh[2][4], bl[2][4];
#pragma unroll
        for (int im = 0; im < 4; im++)
            ldsm_x4(a[im], sA + ((rowA + im * 16) * 72 + ke) * 2);
#pragma unroll
        for (int ib = 0; ib < 2; ib++) {
            ldsm_x4(bh[ib], sBh + ((rowB + ib * 16) * 72 + ke) * 2);
            ldsm_x4(bl[ib], sBl + ((rowB + ib * 16) * 72 + ke) * 2);
        }
#pragma unroll
        for (int im = 0; im < 4; im++) {
#pragma unroll
            for (int in = 0; in < 4; in++) {
                const int ib  = in >> 1;
                const int sel = in & 1;
                mma16816(acc[im][in], a[im], bh[ib][sel], bh[ib][sel + 2]);
                mma16816(acc[im][in], a[im], bl[ib][sel], bl[ib][sel + 2]);
            }
        }
    }
}

#define GEMM_PROLOG() \
    extern __shared__ char smem_c[]; \
    const uint32_t sb = smem_to_u32(smem_c); \
    const int tid  = threadIdx.x; \
    const int wid  = tid >> 5; \
    const int lane = tid & 31; \
    const int wm = (wid & 1) * 64; \
    const int wn = (wid >> 1) * 32; \
    const int rowA  = wm + (lane & 15); \
    const int rowB  = wn + (lane & 15); \
    const int khalf = (lane >> 4) * 8; \
    float acc[4][4][4]; \
    _Pragma("unroll") for (int im = 0; im < 4; im++) \
    _Pragma("unroll") for (int in = 0; in < 4; in++) \
    _Pragma("unroll") for (int e = 0; e < 4; e++) acc[im][in][e] = 0.f;

// ---------------------------------------------------------------------------
// fp32 -> fp16 (elementwise)
// ---------------------------------------------------------------------------
__global__ __launch_bounds__(256) void tohalf_kernel(const float* __restrict__ x, int n)
{
    int i = blockIdx.x * 256 + threadIdx.x;
    if (i < n) g_xh[i] = __float2half_rn(x[i]);
}

// ---------------------------------------------------------------------------
// All 4 weights: [K][N] -> transposed fp16 hi/lo [N][K]. Grid (16,16,4).
// ---------------------------------------------------------------------------
__global__ __launch_bounds__(256) void wsplit4_kernel(
    const float* __restrict__ W0, const float* __restrict__ W1,
    const float* __restrict__ W2, const float* __restrict__ W3)
{
    const int z = blockIdx.z;
    const float* W = (z == 0) ? W0 : (z == 1) ? W1 : (z == 2) ? W2 : W3;
    __shared__ float t[32][33];
    const int tx = threadIdx.x & 31;
    const int ty = threadIdx.x >> 5;
    const int k0 = blockIdx.y * 32;
    const int n0 = blockIdx.x * 32;
#pragma unroll
    for (int i = 0; i < 32; i += 8)
        t[ty + i][tx] = W[(size_t)(k0 + ty + i) * 512 + n0 + tx];
    __syncthreads();
#pragma unroll
    for (int i = 0; i < 32; i += 8) {
        float v = t[tx][ty + i];
        __half h = __float2half_rn(v);
        float r = v - __half2float(h);
        size_t idx = (size_t)(n0 + ty + i) * 512 + k0 + tx;
        g_whi[z][idx] = h;
        g_wlo[z][idx] = __float2half_rn(r);
    }
}

// ---------------------------------------------------------------------------
// Fused QKV projection. Grid (4, 64, 3). z: 0=Q(fp16), 1=K(hi/lo), 2=V(fp32).
// ---------------------------------------------------------------------------
__global__ __launch_bounds__(256, 2) void qkv_kernel(
    const float* __restrict__ bq, const float* __restrict__ bk, const float* __restrict__ bv)
{
    const int z  = blockIdx.z;
    const int m0 = blockIdx.y * 128;
    const int n0 = blockIdx.x * 128;
    const float* bias = (z == 0) ? bq : (z == 1) ? bk : bv;
    const char* A  = (const char*)g_xh;
    const char* Bh = (const char*)g_whi[z];
    const char* Bl = (const char*)g_wlo[z];

    GEMM_PROLOG();

    load_tile2(sb + 0 * TILE_BYTES, A,  1024, m0, 0, tid);
    load_tile2(sb + 1 * TILE_BYTES, Bh, 1024, n0, 0, tid);
    load_tile2(sb + 2 * TILE_BYTES, Bl, 1024, n0, 0, tid);
    cp_commit();

    for (int kc = 0; kc < 8; kc++) {
        const uint32_t cur = sb + (uint32_t)(kc & 1) * STAGE3;
        if (kc < 7) {
            uint32_t nxt = sb + (uint32_t)((kc + 1) & 1) * STAGE3;
            load_tile2(nxt + 0 * TILE_BYTES, A,  1024, m0, kc + 1, tid);
            load_tile2(nxt + 1 * TILE_BYTES, Bh, 1024, n0, kc + 1, tid);
            load_tile2(nxt + 2 * TILE_BYTES, Bl, 1024, n0, kc + 1, tid);
            cp_commit();
            cp_wait1();
        } else {
            cp_wait0();
        }
        __syncthreads();
        mma_chunk2(cur, rowA, rowB, khalf, acc);
        __syncthreads();
    }

    const int gid = lane >> 2;
    const int tg  = lane & 3;
#pragma unroll
    for (int im = 0; im < 4; im++) {
#pragma unroll
        for (int half = 0; half < 2; half++) {
            const int r = m0 + wm + im * 16 + gid + half * 8;
#pragma unroll
            for (int in = 0; in < 4; in++) {
                const int col = n0 + wn + in * 8 + tg * 2;
                float v0 = acc[im][in][half * 2 + 0] + bias[col];
                float v1 = acc[im][in][half * 2 + 1] + bias[col + 1];
                if (z == 0) {
                    *(__half2*)&g_qh[(size_t)r * 512 + col] = __floats2half2_rn(v0, v1);
                } else if (z == 1) {
                    __half h0 = __float2half_rn(v0), h1 = __float2half_rn(v1);
                    *(__half2*)&g_khi[(size_t)r * 512 + col] = __halves2half2(h0, h1);
                    *(__half2*)&g_klo[(size_t)r * 512 + col] =
                        __floats2half2_rn(v0 - __half2float(h0), v1 - __half2float(h1));
                } else {
                    *(float2*)&g_V[(size_t)r * 512 + col] = make_float2(v0, v1);
                }
            }
        }
    }
}

// ---------------------------------------------------------------------------
// Output projection: out = ah @ Wo^T + bo (fp32). Grid (4, 64).
// ---------------------------------------------------------------------------
__global__ __launch_bounds__(256, 2) void out_gemm_kernel(
    const float* __restrict__ bias, float* __restrict__ C)
{
    const int m0 = blockIdx.y * 128;
    const int n0 = blockIdx.x * 128;
    const char* A  = (const char*)g_ah;
    const char* Bh = (const char*)g_whi[3];
    const char* Bl = (const char*)g_wlo[3];

    GEMM_PROLOG();

    load_tile2(sb + 0 * TILE_BYTES, A,  1024, m0, 0, tid);
    load_tile2(sb + 1 * TILE_BYTES, Bh, 1024, n0, 0, tid);
    load_tile2(sb + 2 * TILE_BYTES, Bl, 1024, n0, 0, tid);
    cp_commit();

    for (int kc = 0; kc < 8; kc++) {
        const uint32_t cur = sb + (uint32_t)(kc & 1) * STAGE3;
        if (kc < 7) {
            uint32_t nxt = sb + (uint32_t)((kc + 1) & 1) * STAGE3;
            load_tile2(nxt + 0 * TILE_BYTES, A,  1024, m0, kc + 1, tid);
            load_tile2(nxt + 1 * TILE_BYTES, Bh, 1024, n0, kc + 1, tid);
            load_tile2(nxt + 2 * TILE_BYTES, Bl, 1024, n0, kc + 1, tid);
            cp_commit();
            cp_wait1();
        } else {
            cp_wait0();
        }
        __syncthreads();
        mma_chunk2(cur, rowA, rowB, khalf, acc);
        __syncthreads();
    }

    const int gid = lane >> 2;
    const int tg  = lane & 3;
#pragma unroll
    for (int im = 0; im < 4; im++) {
        const int r0 = m0 + wm + im * 16 + gid;
        const int r1 = r0 + 8;
#pragma unroll
        for (int in = 0; in < 4; in++) {
            const int col = n0 + wn + in * 8 + tg * 2;
            const float b0 = bias[col], b1 = bias[col + 1];
            *(float2*)(C + (size_t)r0 * 512 + col) = make_float2(acc[im][in][0] + b0, acc[im][in][1] + b1);
            *(float2*)(C + (size_t)r1 * 512 + col) = make_float2(acc[im][in][2] + b0, acc[im][in][3] + b1);
        }
    }
}

// ---------------------------------------------------------------------------
// Build per-group row lists (deterministic ascending). Grid = 64.
// ---------------------------------------------------------------------------
__global__ __launch_bounds__(256) void build_lists_kernel(const int* __restrict__ labels)
{
    __shared__ int s_cnt[256], s_pre[256], s_list[512];
    const int g    = blockIdx.x;
    const int tid  = threadIdx.x;
    const int warp = tid >> 5;
    const int lane = tid & 31;

    for (int c = warp; c < 256; c += 8) {
        int lab = labels[c * 32 + lane];
        unsigned m = __ballot_sync(0xffffffffu, lab == g);
        if (lane == 0) s_cnt[c] = __popc(m);
    }
    __syncthreads();
    if (warp == 0) {
        int vals[8];
        int run = 0;
#pragma unroll
        for (int j = 0; j < 8; j++) { int t = s_cnt[lane * 8 + j]; vals[j] = run; run += t; }
        int x = run;
#pragma unroll
        for (int off = 1; off < 32; off <<= 1) {
            int y = __shfl_up_sync(0xffffffffu, x, off);
            if (lane >= off) x += y;
        }
        int excl = x - run;
#pragma unroll
        for (int j = 0; j < 8; j++) s_pre[lane * 8 + j] = excl + vals[j];
    }
    __syncthreads();
    const int n = s_pre[255] + s_cnt[255];
    for (int c = warp; c < 256; c += 8) {
        int lab = labels[c * 32 + lane];
        unsigned m = __ballot_sync(0xffffffffu, lab == g);
        if (lab == g) {
            int idx = s_pre[c] + __popc(m & ((1u << lane) - 1));
            if (idx < 512) s_list[idx] = c * 32 + lane;
        }
    }
    __syncthreads();
    if (tid < CAP) g_list[g][tid] = (tid < n) ? s_list[tid] : 0;
    if (tid == 0) g_cnt[g] = (n > CAP) ? CAP : n;
}

// ---------------------------------------------------------------------------
// Gather + transpose + split V -> VT[g][dim][key] fp16 hi/lo. Grid (64, 8).
// ---------------------------------------------------------------------------
__global__ __launch_bounds__(256) void vt_build_kernel()
{
    const int g  = blockIdx.x;
    const int kt = blockIdx.y;
    const int n  = g_cnt[g];
    if (kt * 32 >= n) return;

    __shared__ float t[32][33];
    __shared__ int rows[32];
    const int tx = threadIdx.x & 31;
    const int ty = threadIdx.x >> 5;
    if (threadIdx.x < 32) {
        int key = kt * 32 + threadIdx.x;
        rows[threadIdx.x] = (key < n) ? g_list[g][key] : -1;
    }
    __syncthreads();

    for (int db = 0; db < 16; db++) {
#pragma unroll
        for (int i = 0; i < 32; i += 8) {
            int r = rows[ty + i];
            t[ty + i][tx] = (r >= 0) ? g_V[(size_t)r * 512 + db * 32 + tx] : 0.f;
        }
        __syncthreads();
#pragma unroll
        for (int i = 0; i < 32; i += 8) {
            int d = db * 32 + ty + i;
            int k = kt * 32 + tx;
            if (k < n) {
                float v = t[tx][ty + i];
                __half h = __float2half_rn(v);
                g_VThi[g][d * CAP + k] = h;
                g_VTlo[g][d * CAP + k] = __float2half_rn(v - __half2float(h));
            }
        }
        __syncthreads();
    }
}

// ---------------------------------------------------------------------------
// Scores: S_g = scale * Qh_g @ (Khi+Klo)_g^T. Grid (64,2,2), indirect rows.
// ---------------------------------------------------------------------------
__global__ __launch_bounds__(256, 2) void scores_mma_kernel()
{
    const int g  = blockIdx.x;
    const int n  = g_cnt[g];
    const int n0 = blockIdx.y * 128;
    const int m0 = blockIdx.z * 128;
    if (m0 >= n || n0 >= n) return;

    __shared__ int rA[128], rB[128];
    GEMM_PROLOG();

    if (tid < 128) rA[tid] = g_list[g][m0 + tid];
    else           rB[tid - 128] = g_list[g][n0 + tid - 128];
    __syncthreads();

    load_tile_idx(sb + 0 * TILE_BYTES, (const char*)g_qh,  rA, 0, tid);
    load_tile_idx(sb + 1 * TILE_BYTES, (const char*)g_khi, rB, 0, tid);
    load_tile_idx(sb + 2 * TILE_BYTES, (const char*)g_klo, rB, 0, tid);
    cp_commit();

    for (int kc = 0; kc < 8; kc++) {
        const uint32_t cur = sb + (uint32_t)(kc & 1) * STAGE3;
        if (kc < 7) {
            uint32_t nxt = sb + (uint32_t)((kc + 1) & 1) * STAGE3;
            load_tile_idx(nxt + 0 * TILE_BYTES, (const char*)g_qh,  rA, kc + 1, tid);
            load_tile_idx(nxt + 1 * TILE_BYTES, (const char*)g_khi, rB, kc + 1, tid);
            load_tile_idx(nxt + 2 * TILE_BYTES, (const char*)g_klo, rB, kc + 1, tid);
            cp_commit();
            cp_wait1();
        } else {
            cp_wait0();
        }
        __syncthreads();
        mma_chunk2(cur, rowA, rowB, khalf, acc);
        __syncthreads();
    }

    const float scale = 0.04419417382415922f;  // 1/sqrt(512)
    float* S = g_S[g];
    const int gid = lane >> 2;
    const int tg  = lane & 3;
#pragma unroll
    for (int im = 0; im < 4; im++) {
        const int r0 = m0 + wm + im * 16 + gid;
        const int r1 = r0 + 8;
#pragma unroll
        for (int in = 0; in < 4; in++) {
            const int col = n0 + wn + in * 8 + tg * 2;
            *(float2*)(S + (size_t)r0 * CAP + col) =
                make_float2(acc[im][in][0] * scale, acc[im][in][1] * scale);
            *(float2*)(S + (size_t)r1 * CAP + col) =
                make_float2(acc[im][in][2] * scale, acc[im][in][3] * scale);
        }
    }
}

// ---------------------------------------------------------------------------
// Softmax over valid keys -> P fp16 (zero-padded to 64-multiple). Grid (64,8).
// ---------------------------------------------------------------------------
__global__ __launch_bounds__(256) void softmax_kernel()
{
    const int g  = blockIdx.x;
    const int rb = blockIdx.y;
    const int n  = g_cnt[g];
    const int np = (n + 63) & ~63;
    const int warp = threadIdx.x >> 5;
    const int lane = threadIdx.x & 31;

    for (int rr = 0; rr < 4; rr++) {
        const int r = rb * 32 + rr * 8 + warp;
        if (r >= n) continue;
        const float* srow = g_S[g] + (size_t)r * CAP;
        float s[8];
        float mx = -INFINITY;
#pragma unroll
        for (int j = 0; j < 8; j++) {
            int k = lane + 32 * j;
            s[j] = (k < n) ? srow[k] : -INFINITY;
            mx = fmaxf(mx, s[j]);
        }
#pragma unroll
        for (int off = 16; off > 0; off >>= 1)
            mx = fmaxf(mx, __shfl_xor_sync(0xffffffffu, mx, off));
        float sum = 0.f;
#pragma unroll
        for (int j = 0; j < 8; j++) {
            s[j] = (lane + 32 * j < n) ? __expf(s[j] - mx) : 0.f;
            sum += s[j];
        }
#pragma unroll
        for (int off = 16; off > 0; off >>= 1)
            sum += __shfl_xor_sync(0xffffffffu, sum, off);
        const float inv = 1.0f / sum;
#pragma unroll
        for (int j = 0; j < 8; j++) {
            int k = lane + 32 * j;
            if (k < np) g_Ph[g][(size_t)r * CAP + k] = __float2half_rn(s[j] * inv);
        }
    }
}

// ---------------------------------------------------------------------------
// PV: O_g = P_g @ V_g -> scatter fp16 rows into g_ah. Grid (64, 4, 2).
// ---------------------------------------------------------------------------
__global__ __launch_bounds__(256, 2) void pv_mma_kernel()
{
    const int g  = blockIdx.x;
    const int n  = g_cnt[g];
    const int n0 = blockIdx.y * 128;   // dim tile
    const int m0 = blockIdx.z * 128;   // query tile
    if (m0 >= n) return;
    const int nch = ((n + 63) & ~63) >> 6;

    __shared__ int rO[128];
    GEMM_PROLOG();

    if (tid < 128) rO[tid] = g_list[g][m0 + tid];
    __syncthreads();

    const char* P   = (const char*)g_Ph[g];
    const char* VTh = (const char*)g_VThi[g];
    const char* VTl = (const char*)g_VTlo[g];

    load_tile2(sb + 0 * TILE_BYTES, P,   CAP * 2, m0, 0, tid);
    load_tile2(sb + 1 * TILE_BYTES, VTh, CAP * 2, n0, 0, tid);
    load_tile2(sb + 2 * TILE_BYTES, VTl, CAP * 2, n0, 0, tid);
    cp_commit();

    for (int kc = 0; kc < nch; kc++) {
        const uint32_t cur = sb + (uint32_t)(kc & 1) * STAGE3;
        if (kc + 1 < nch) {
            uint32_t nxt = sb + (uint32_t)((kc + 1) & 1) * STAGE3;
            load_tile2(nxt + 0 * TILE_BYTES, P,   CAP * 2, m0, kc + 1, tid);
            load_tile2(nxt + 1 * TILE_BYTES, VTh, CAP * 2, n0, kc + 1, tid);
            load_tile2(nxt + 2 * TILE_BYTES, VTl, CAP * 2, n0, kc + 1, tid);
            cp_commit();
            cp_wait1();
        } else {
            cp_wait0();
        }
        __syncthreads();
        mma_chunk2(cur, rowA, rowB, khalf, acc);
        __syncthreads();
    }

    const int gid = lane >> 2;
    const int tg  = lane & 3;
#pragma unroll
    for (int im = 0; im < 4; im++) {
        const int lr0 = wm + im * 16 + gid;
        const int lr1 = lr0 + 8;
#pragma unroll
        for (int in = 0; in < 4; in++) {
            const int col = n0 + wn + in * 8 + tg * 2;
            if (m0 + lr0 < n)
                *(__half2*)&g_ah[(size_t)rO[lr0] * 512 + col] =
                    __floats2half2_rn(acc[im][in][0], acc[im][in][1]);
            if (m0 + lr1 < n)
                *(__half2*)&g_ah[(size_t)rO[lr1] * 512 + col] =
                    __floats2half2_rn(acc[im][in][2], acc[im][in][3]);
        }
    }
}

// ---------------------------------------------------------------------------
// Zero ah rows with label == -1.
// ---------------------------------------------------------------------------
__global__ __launch_bounds__(64) void zero_invalid_kernel(const int* __restrict__ labels)
{
    const int row = blockIdx.x;
    if (labels[row] >= 0) return;
    ((uint4*)(g_ah + (size_t)row * 512))[threadIdx.x] = make_uint4(0, 0, 0, 0);
}

// ---------------------------------------------------------------------------
extern "C" void kernel_launch(void* const* d_in, const int* in_sizes, int n_in,
                              void* d_out, int out_size)
{
    const float* x      = (const float*)d_in[0];
    const int*   labels = (const int*)  d_in[1];
    const float* Wq     = (const float*)d_in[2];
    const float* bq     = (const float*)d_in[3];
    const float* Wk     = (const float*)d_in[4];
    const float* bk     = (const float*)d_in[5];
    const float* Wv     = (const float*)d_in[6];
    const float* bv     = (const float*)d_in[7];
    const float* Wo     = (const float*)d_in[8];
    const float* bo     = (const float*)d_in[9];
    float* out = (float*)d_out;

    cudaFuncSetAttribute(qkv_kernel,        cudaFuncAttributeMaxDynamicSharedMemorySize, SMEM3);
    cudaFuncSetAttribute(out_gemm_kernel,   cudaFuncAttributeMaxDynamicSharedMemorySize, SMEM3);
    cudaFuncSetAttribute(scores_mma_kernel, cudaFuncAttributeMaxDynamicSharedMemorySize, SMEM3);
    cudaFuncSetAttribute(pv_mma_kernel,     cudaFuncAttributeMaxDynamicSharedMemorySize, SMEM3);
    // Max smem carveout so two 110.6 KB CTAs co-reside per SM.
    cudaFuncSetAttribute(qkv_kernel,        cudaFuncAttributePreferredSharedMemoryCarveout, 100);
    cudaFuncSetAttribute(out_gemm_kernel,   cudaFuncAttributePreferredSharedMemoryCarveout, 100);
    cudaFuncSetAttribute(scores_mma_kernel, cudaFuncAttributePreferredSharedMemoryCarveout, 100);
    cudaFuncSetAttribute(pv_mma_kernel,     cudaFuncAttributePreferredSharedMemoryCarveout, 100);

    const int nelem = NROWS * DIM;
    tohalf_kernel<<<nelem / 256, 256>>>(x, nelem);
    wsplit4_kernel<<<dim3(16, 16, 4), 256>>>(Wq, Wk, Wv, Wo);
    build_lists_kernel<<<NG, 256>>>(labels);

    qkv_kernel<<<dim3(4, 64, 3), 256, SMEM3>>>(bq, bk, bv);

    vt_build_kernel<<<dim3(NG, CAP / 32), 256>>>();
    scores_mma_kernel<<<dim3(NG, 2, 2), 256, SMEM3>>>();
    softmax_kernel<<<dim3(NG, CAP / 32), 256>>>();
    pv_mma_kernel<<<dim3(NG, 4, 2), 256, SMEM3>>>();
    zero_invalid_kernel<<<NROWS, 64>>>(labels);

    out_gemm_kernel<<<dim3(4, 64), 256, SMEM3>>>(bo, out);
}